// round 9
// baseline (speedup 1.0000x reference)
#include <cuda_runtime.h>
#include <cuda_bf16.h>
#include <mma.h>
#include <math.h>

#define B_     8
#define C_     256
#define NPIX   4096
#define SROW   40
#define FE_PAD 68

using namespace nvcuda;

// q hi rows [0,32), k hi [32,64), q lo [64,96), k lo [96,128)
__device__ __nv_bfloat16  g_qkb[(size_t)B_ * 128 * NPIX];
__device__ __nv_bfloat16  g_vb[(size_t)B_ * C_ * NPIX];
__device__ __nv_bfloat16  g_attb[(size_t)B_ * NPIX * NPIX];

// ---------------------------------------------------------------------------
// K1: fused QKV projection. q/k rows -> g_qkb as bf16 hi/lo split,
// v rows -> g_vb (bf16).
// ---------------------------------------------------------------------------
__global__ void proj_kernel(const float* __restrict__ x,
                            const float* __restrict__ Wq, const float* __restrict__ bq,
                            const float* __restrict__ Wk, const float* __restrict__ bk,
                            const float* __restrict__ Wv, const float* __restrict__ bv) {
    __shared__ float As[64 * 32];
    __shared__ __align__(16) float Xs[32 * 64];

    const int b  = blockIdx.z;
    const int o0 = blockIdx.y * 64;
    const int n0 = blockIdx.x * 64;
    const int tid = threadIdx.x;
    const int tx = tid & 15;
    const int ty = tid >> 4;

    const float* xb = x + (size_t)b * C_ * NPIX;
    float acc[4][4] = { };

    for (int k0 = 0; k0 < C_; k0 += 32) {
        const int wo = tid >> 2;
        const int wcid = (tid & 3) * 8;
        const int go = o0 + wo;
        const float* Wrow;
        if (go < 32) {
            Wrow = Wq + go * C_;
        } else if (go < 64) {
            Wrow = Wk + (go - 32) * C_;
        } else {
            Wrow = Wv + (go - 64) * C_;
        }
        #pragma unroll
        for (int u = 0; u < 8; ++u) As[wo * 32 + wcid + u] = Wrow[k0 + wcid + u];

        const int kk2 = tid >> 3;
        const int nj2 = (tid & 7) * 8;
        const float* xr = xb + (size_t)(k0 + kk2) * NPIX + n0 + nj2;
        #pragma unroll
        for (int u = 0; u < 8; ++u) Xs[kk2 * 64 + nj2 + u] = xr[u];

        __syncthreads();
        #pragma unroll
        for (int kk = 0; kk < 32; ++kk) {
            float4 xv = *(const float4*)&Xs[kk * 64 + tx * 4];
            #pragma unroll
            for (int ii = 0; ii < 4; ++ii) {
                float a = As[(ty * 4 + ii) * 32 + kk];
                acc[ii][0] += a * xv.x;
                acc[ii][1] += a * xv.y;
                acc[ii][2] += a * xv.z;
                acc[ii][3] += a * xv.w;
            }
        }
        __syncthreads();
    }

    #pragma unroll
    for (int ii = 0; ii < 4; ++ii) {
        const int o = o0 + ty * 4 + ii;
        float bias;
        if (o < 32) {
            bias = bq[o];
        } else if (o < 64) {
            bias = bk[o - 32];
        } else {
            bias = bv[o - 64];
        }
        if (o < 64) {
            __nv_bfloat16* dhi = g_qkb + ((size_t)b * 128 + o) * NPIX + n0 + tx * 4;
            __nv_bfloat16* dlo = dhi + (size_t)64 * NPIX;
            #pragma unroll
            for (int jj = 0; jj < 4; ++jj) {
                float val = acc[ii][jj] + bias;
                __nv_bfloat16 h = __float2bfloat16(val);
                dhi[jj] = h;
                dlo[jj] = __float2bfloat16(val - __bfloat162float(h));
            }
        } else {
            __nv_bfloat16* dst = g_vb + ((size_t)b * C_ + (o - 64)) * NPIX + n0 + tx * 4;
            #pragma unroll
            for (int jj = 0; jj < 4; ++jj) dst[jj] = __float2bfloat16(acc[ii][jj] + bias);
        }
    }
}

// ---------------------------------------------------------------------------
// K2: FUSED energy + softmax. One CTA = 128 full attention rows.
// Pass 1: recomputable split-bf16 energy tiles -> per-row sum of exp(e)
//         (no max subtraction: |e| <= ~4, exp safe in fp32).
// Pass 2: recompute identical energy, write exp(e)*inv fp32 + bf16.
// ---------------------------------------------------------------------------
__global__ void __launch_bounds__(256)
fused_attn_kernel(float* __restrict__ att) {
    __shared__ __align__(16) float stage[8 * 32 * FE_PAD];
    __shared__ float partsum[8][32];
    __shared__ float rowinv[128];

    const int b  = blockIdx.y;
    const int n0 = blockIdx.x * 128;
    const int tid  = threadIdx.x;
    const int warp = tid >> 5;
    const int lane = tid & 31;
    const int wn = (warp & 3) * 32;
    const int wm = (warp >> 2) * 64;

    const __nv_bfloat16* qh = g_qkb + (size_t)b * 128 * NPIX;
    const __nv_bfloat16* kh = qh + (size_t)32 * NPIX;
    const __nv_bfloat16* ql = qh + (size_t)64 * NPIX;
    const __nv_bfloat16* kl = qh + (size_t)96 * NPIX;

    float* mystage = stage + warp * (32 * FE_PAD);

    // Hoisted A fragments (constant across all m-tiles)
    wmma::fragment<wmma::matrix_a, 16, 16, 16, __nv_bfloat16, wmma::col_major> ah[2][2], al[2][2];
    #pragma unroll
    for (int ks = 0; ks < 2; ++ks) {
        #pragma unroll
        for (int i = 0; i < 2; ++i) {
            wmma::load_matrix_sync(ah[ks][i], qh + (size_t)(ks * 16) * NPIX + n0 + wn + 16 * i, NPIX);
            wmma::load_matrix_sync(al[ks][i], ql + (size_t)(ks * 16) * NPIX + n0 + wn + 16 * i, NPIX);
        }
    }

    float rs0 = 0.f, rs1 = 0.f, rs2 = 0.f, rs3 = 0.f;

    // ---------------- PASS 1: row sums of exp(energy) ----------------
    for (int mt = 0; mt < 32; ++mt) {
        const int m0 = mt * 128;
        wmma::fragment<wmma::accumulator, 16, 16, 16, float> acc[2][4];
        #pragma unroll
        for (int i = 0; i < 2; ++i) {
            #pragma unroll
            for (int j = 0; j < 4; ++j) wmma::fill_fragment(acc[i][j], 0.0f);
        }
        #pragma unroll
        for (int ks = 0; ks < 2; ++ks) {
            wmma::fragment<wmma::matrix_b, 16, 16, 16, __nv_bfloat16, wmma::row_major> bh[4], bl[4];
            #pragma unroll
            for (int j = 0; j < 4; ++j) {
                wmma::load_matrix_sync(bh[j], kh + (size_t)(ks * 16) * NPIX + m0 + wm + 16 * j, NPIX);
                wmma::load_matrix_sync(bl[j], kl + (size_t)(ks * 16) * NPIX + m0 + wm + 16 * j, NPIX);
            }
            #pragma unroll
            for (int i = 0; i < 2; ++i) {
                #pragma unroll
                for (int j = 0; j < 4; ++j) {
                    wmma::mma_sync(acc[i][j], ah[ks][i], bl[j], acc[i][j]);
                    wmma::mma_sync(acc[i][j], al[ks][i], bh[j], acc[i][j]);
                    wmma::mma_sync(acc[i][j], ah[ks][i], bh[j], acc[i][j]);
                }
            }
        }
        __syncwarp();   // prior iteration's reads complete before overwrite
        #pragma unroll
        for (int i = 0; i < 2; ++i) {
            #pragma unroll
            for (int j = 0; j < 4; ++j) {
                wmma::store_matrix_sync(mystage + (16 * i) * FE_PAD + 16 * j, acc[i][j],
                                        FE_PAD, wmma::mem_row_major);
            }
        }
        __syncwarp();
        // Per-lane scan of own row; stride-29 rotation keeps banks distinct.
        const float* srow = mystage + lane * FE_PAD;
        int cc = (29 * lane) & 63;
        #pragma unroll
        for (int i = 0; i < 16; ++i) {
            rs0 += __expf(srow[cc]);             cc = (cc + 1) & 63;
            rs1 += __expf(srow[cc]);             cc = (cc + 1) & 63;
            rs2 += __expf(srow[cc]);             cc = (cc + 1) & 63;
            rs3 += __expf(srow[cc]);             cc = (cc + 1) & 63;
        }
    }
    partsum[warp][lane] = (rs0 + rs1) + (rs2 + rs3);
    __syncthreads();
    if (warp < 4) {
        float tot = partsum[warp][lane] + partsum[warp + 4][lane];
        rowinv[wn + lane] = 1.0f / tot;
    }
    __syncthreads();

    float* ab = att + ((size_t)b * NPIX + n0) * NPIX;
    __nv_bfloat16* abb = g_attb + ((size_t)b * NPIX + n0) * NPIX;

    // ---------------- PASS 2: write normalized attention ----------------
    for (int mt = 0; mt < 32; ++mt) {
        const int m0 = mt * 128;
        wmma::fragment<wmma::accumulator, 16, 16, 16, float> acc[2][4];
        #pragma unroll
        for (int i = 0; i < 2; ++i) {
            #pragma unroll
            for (int j = 0; j < 4; ++j) wmma::fill_fragment(acc[i][j], 0.0f);
        }
        #pragma unroll
        for (int ks = 0; ks < 2; ++ks) {
            wmma::fragment<wmma::matrix_b, 16, 16, 16, __nv_bfloat16, wmma::row_major> bh[4], bl[4];
            #pragma unroll
            for (int j = 0; j < 4; ++j) {
                wmma::load_matrix_sync(bh[j], kh + (size_t)(ks * 16) * NPIX + m0 + wm + 16 * j, NPIX);
                wmma::load_matrix_sync(bl[j], kl + (size_t)(ks * 16) * NPIX + m0 + wm + 16 * j, NPIX);
            }
            #pragma unroll
            for (int i = 0; i < 2; ++i) {
                #pragma unroll
                for (int j = 0; j < 4; ++j) {
                    wmma::mma_sync(acc[i][j], ah[ks][i], bl[j], acc[i][j]);
                    wmma::mma_sync(acc[i][j], al[ks][i], bh[j], acc[i][j]);
                    wmma::mma_sync(acc[i][j], ah[ks][i], bh[j], acc[i][j]);
                }
            }
        }
        __syncthreads();   // prior tile's cooperative reads complete
        #pragma unroll
        for (int i = 0; i < 2; ++i) {
            #pragma unroll
            for (int j = 0; j < 4; ++j) {
                wmma::store_matrix_sync(mystage + (16 * i) * FE_PAD + 16 * j, acc[i][j],
                                        FE_PAD, wmma::mem_row_major);
            }
        }
        __syncthreads();   // full tile staged
        // Cooperative coalesced write: warp w owns rows [16w, 16w+16)
        #pragma unroll
        for (int r8 = 0; r8 < 16; ++r8) {
            const int r = warp * 16 + r8;
            const float inv = rowinv[r];
            const int sw = r >> 5;
            #pragma unroll
            for (int it = 0; it < 4; ++it) {
                const int c = it * 32 + lane;
                const float e = stage[(sw + 4 * (c >> 6)) * (32 * FE_PAD)
                                      + (r & 31) * FE_PAD + (c & 63)];
                const float p = __expf(e) * inv;
                ab[(size_t)r * NPIX + m0 + c]  = p;
                abb[(size_t)r * NPIX + m0 + c] = __float2bfloat16(p);
            }
        }
        __syncthreads();
    }
}

// ---------------------------------------------------------------------------
// K3: tensor-core AV GEMM. 128 threads, 4 warps of 64x64 (256B smem per mma).
//   out[c,n] = 0.5*gamma*sum_m v[c,m]*att[n,m] + x[c,n]
// ---------------------------------------------------------------------------
__global__ void __launch_bounds__(128, 2)
av_wmma_kernel(const float* __restrict__ x, const float* __restrict__ gamma,
               float* __restrict__ out) {
    __shared__ __align__(256) __nv_bfloat16 As[2][128 * SROW];
    __shared__ __align__(256) __nv_bfloat16 Bs[2][128 * SROW];

    const int b    = blockIdx.z;
    const int c0   = blockIdx.y * 128;
    const int n0   = blockIdx.x * 128;
    const int tid  = threadIdx.x;
    const int warp = tid >> 5;
    const int lane = tid & 31;
    const int wc   = (warp & 1) * 64;
    const int wn   = (warp >> 1) * 64;

    const __nv_bfloat16* vb = g_vb   + (size_t)b * C_ * NPIX;
    const __nv_bfloat16* ab = g_attb + (size_t)b * NPIX * NPIX;

    const __nv_bfloat16* gA = vb + (size_t)(c0 + tid) * NPIX;
    const __nv_bfloat16* gB = ab + (size_t)(n0 + tid) * NPIX;
    const int sOff = tid * SROW;

    wmma::fragment<wmma::accumulator, 16, 16, 16, float> acc[4][4];
    #pragma unroll
    for (int i = 0; i < 4; ++i) {
        #pragma unroll
        for (int j = 0; j < 4; ++j) wmma::fill_fragment(acc[i][j], 0.0f);
    }

    #pragma unroll
    for (int q = 0; q < 4; ++q) {
        *(uint4*)&As[0][sOff + 8 * q] = *(const uint4*)(gA + 8 * q);
        *(uint4*)&Bs[0][sOff + 8 * q] = *(const uint4*)(gB + 8 * q);
    }
    __syncthreads();

    for (int it = 0; it < 128; ++it) {
        const int cur = it & 1;
        uint4 na[4], nb[4];
        if (it < 127) {
            const __nv_bfloat16* pA = gA + (it + 1) * 32;
            const __nv_bfloat16* pB = gB + (it + 1) * 32;
            #pragma unroll
            for (int q = 0; q < 4; ++q) {
                na[q] = *(const uint4*)(pA + 8 * q);
                nb[q] = *(const uint4*)(pB + 8 * q);
            }
        }

        const __nv_bfloat16* Ab = &As[cur][0];
        const __nv_bfloat16* Bb = &Bs[cur][0];

        #pragma unroll
        for (int kk = 0; kk < 32; kk += 16) {
            wmma::fragment<wmma::matrix_a, 16, 16, 16, __nv_bfloat16, wmma::row_major> afrag[4];
            wmma::fragment<wmma::matrix_b, 16, 16, 16, __nv_bfloat16, wmma::col_major> bfrag[4];
            #pragma unroll
            for (int i = 0; i < 4; ++i) {
                wmma::load_matrix_sync(afrag[i], Ab + (wc + 16 * i) * SROW + kk, SROW);
            }
            #pragma unroll
            for (int j = 0; j < 4; ++j) {
                wmma::load_matrix_sync(bfrag[j], Bb + (wn + 16 * j) * SROW + kk, SROW);
            }
            #pragma unroll
            for (int i = 0; i < 4; ++i) {
                #pragma unroll
                for (int j = 0; j < 4; ++j) {
                    wmma::mma_sync(acc[i][j], afrag[i], bfrag[j], acc[i][j]);
                }
            }
        }

        if (it < 127) {
            const int nxt = cur ^ 1;
            #pragma unroll
            for (int q = 0; q < 4; ++q) {
                *(uint4*)&As[nxt][sOff + 8 * q] = na[q];
                *(uint4*)&Bs[nxt][sOff + 8 * q] = nb[q];
            }
        }
        __syncthreads();
    }

    const float g = 0.5f * gamma[0];
    const float* xb = x   + (size_t)b * C_ * NPIX;
    float*       ob = out + (size_t)b * C_ * NPIX;
    float* stage = (float*)(&As[0][0]) + warp * 256;

    const int srow = lane >> 1;
    const int scol = (lane & 1) * 8;

    #pragma unroll
    for (int i = 0; i < 4; ++i) {
        #pragma unroll
        for (int j = 0; j < 4; ++j) {
            wmma::store_matrix_sync(stage, acc[i][j], 16, wmma::mem_row_major);
            __syncwarp();
            const int cc = c0 + wc + 16 * i + srow;
            const int nn = n0 + wn + 16 * j + scol;
            const size_t off = (size_t)cc * NPIX + nn;
            float4 s0 = *(const float4*)&stage[srow * 16 + scol];
            float4 s1 = *(const float4*)&stage[srow * 16 + scol + 4];
            float4 xv0 = *(const float4*)&xb[off];
            float4 xv1 = *(const float4*)&xb[off + 4];
            float4 ov0;
            float4 ov1;
            ov0.x = g * s0.x + xv0.x;
            ov0.y = g * s0.y + xv0.y;
            ov0.z = g * s0.z + xv0.z;
            ov0.w = g * s0.w + xv0.w;
            ov1.x = g * s1.x + xv1.x;
            ov1.y = g * s1.y + xv1.y;
            ov1.z = g * s1.z + xv1.z;
            ov1.w = g * s1.w + xv1.w;
            *(float4*)&ob[off]     = ov0;
            *(float4*)&ob[off + 4] = ov1;
            __syncwarp();
        }
    }
}

// ---------------------------------------------------------------------------
extern "C" void kernel_launch(void* const* d_in, const int* in_sizes, int n_in,
                              void* d_out, int out_size) {
    const float* x     = (const float*)d_in[0];
    const float* Wq    = (const float*)d_in[1];
    const float* bq    = (const float*)d_in[2];
    const float* Wk    = (const float*)d_in[3];
    const float* bk    = (const float*)d_in[4];
    const float* Wv    = (const float*)d_in[5];
    const float* bv    = (const float*)d_in[6];
    const float* gamma = (const float*)d_in[7];

    float* out = (float*)d_out;
    float* att = out + (size_t)B_ * C_ * NPIX;

    proj_kernel<<<dim3(64, 5, B_), 256>>>(x, Wq, bq, Wk, bk, Wv, bv);
    fused_attn_kernel<<<dim3(32, B_), 256>>>(att);
    av_wmma_kernel<<<dim3(32, 2, B_), 128>>>(x, gamma, out);
}